// round 2
// baseline (speedup 1.0000x reference)
#include <cuda_runtime.h>
#include <math.h>

// Problem shape (fixed by reference)
namespace {
constexpr int B  = 4, H = 16, S = 2048, D = 64;
constexpr int BM = 64;   // query rows per CTA
constexpr int BN = 64;   // key cols per tile
constexpr int PAD = 68;  // row stride (floats) for transposed tiles: 272B, 16B-aligned,
                         // makes both the transpose STS and the float4 LDS conflict-free
constexpr int SM_QT = 0;            // Qt[d][row]   : D x PAD
constexpr int SM_KP = D * PAD;      // Kt[d][col] then Pt[key][row] (aliased) : 64 x PAD
constexpr int SM_V  = 2 * D * PAD;  // Vs[key][d]   : BN x D (row-major, no pad needed)
constexpr int SMEM_FLOATS = 2 * D * PAD + BN * D;   // 12800 floats = 51200 B
constexpr float SCALE = 0.125f;     // 1/sqrt(64)
constexpr float NEGC  = -1e9f;
}

__global__ __launch_bounds__(256) void attn_fwd(
    const float* __restrict__ Q, const float* __restrict__ K,
    const float* __restrict__ V, const int* __restrict__ Mask,
    float* __restrict__ Out)
{
    extern __shared__ float sm[];
    float* Qt  = sm + SM_QT;
    float* KPt = sm + SM_KP;
    float* Vs  = sm + SM_V;

    const int tid = threadIdx.x;
    const int tx  = tid & 15;   // 0..15 -> 4 key-cols / 4 D-cols
    const int ty  = tid >> 4;   // 0..15 -> 4 query-rows
    const int bh  = blockIdx.y;         // b*H + h
    const int b   = bh >> 4;            // H == 16
    const int qbase = blockIdx.x * BM;

    const float* qp = Q + (size_t)bh * S * D;
    const float* kp = K + (size_t)bh * S * D;
    const float* vp = V + (size_t)bh * S * D;
    const int*   mp = Mask + (size_t)b * S * S + (size_t)qbase * S;

    // ---- load Q tile transposed: Qt[d][row]  (column-mapped loader -> conflict-free STS)
    #pragma unroll
    for (int rr = 0; rr < BM; rr += 16) {
        const int r  = rr + tx;
        const int d0 = ty * 4;
        float4 t = *reinterpret_cast<const float4*>(qp + (size_t)(qbase + r) * D + d0);
        Qt[(d0 + 0) * PAD + r] = t.x;
        Qt[(d0 + 1) * PAD + r] = t.y;
        Qt[(d0 + 2) * PAD + r] = t.z;
        Qt[(d0 + 3) * PAD + r] = t.w;
    }

    float acc[4][4];
    float m_i[4], l_i[4];
    #pragma unroll
    for (int i = 0; i < 4; ++i) {
        m_i[i] = -1e30f; l_i[i] = 0.f;
        #pragma unroll
        for (int j = 0; j < 4; ++j) acc[i][j] = 0.f;
    }

    for (int t = 0; t < S / BN; ++t) {
        const int kbase = t * BN;

        // ---- K tile transposed: Kt[d][col]
        #pragma unroll
        for (int rr = 0; rr < BN; rr += 16) {
            const int r  = rr + tx;
            const int d0 = ty * 4;
            float4 tk = *reinterpret_cast<const float4*>(kp + (size_t)(kbase + r) * D + d0);
            KPt[(d0 + 0) * PAD + r] = tk.x;
            KPt[(d0 + 1) * PAD + r] = tk.y;
            KPt[(d0 + 2) * PAD + r] = tk.z;
            KPt[(d0 + 3) * PAD + r] = tk.w;
        }
        // ---- V tile row-major: Vs[key][d]
        #pragma unroll
        for (int rr = 0; rr < BN; rr += 16) {
            const int r = rr + ty;
            float4 tv = *reinterpret_cast<const float4*>(vp + (size_t)(kbase + r) * D + tx * 4);
            *reinterpret_cast<float4*>(Vs + r * D + tx * 4) = tv;
        }
        __syncthreads();

        // ---- GEMM1: s[4][4] = Q K^T  (rows ty*4+i, cols tx*4+j)
        float s[4][4];
        #pragma unroll
        for (int i = 0; i < 4; ++i)
            #pragma unroll
            for (int j = 0; j < 4; ++j) s[i][j] = 0.f;

        #pragma unroll 8
        for (int kk = 0; kk < D; ++kk) {
            float4 a  = *reinterpret_cast<const float4*>(Qt  + kk * PAD + ty * 4);
            float4 bb = *reinterpret_cast<const float4*>(KPt + kk * PAD + tx * 4);
            s[0][0] = fmaf(a.x, bb.x, s[0][0]); s[0][1] = fmaf(a.x, bb.y, s[0][1]);
            s[0][2] = fmaf(a.x, bb.z, s[0][2]); s[0][3] = fmaf(a.x, bb.w, s[0][3]);
            s[1][0] = fmaf(a.y, bb.x, s[1][0]); s[1][1] = fmaf(a.y, bb.y, s[1][1]);
            s[1][2] = fmaf(a.y, bb.z, s[1][2]); s[1][3] = fmaf(a.y, bb.w, s[1][3]);
            s[2][0] = fmaf(a.z, bb.x, s[2][0]); s[2][1] = fmaf(a.z, bb.y, s[2][1]);
            s[2][2] = fmaf(a.z, bb.z, s[2][2]); s[2][3] = fmaf(a.z, bb.w, s[2][3]);
            s[3][0] = fmaf(a.w, bb.x, s[3][0]); s[3][1] = fmaf(a.w, bb.y, s[3][1]);
            s[3][2] = fmaf(a.w, bb.z, s[3][2]); s[3][3] = fmaf(a.w, bb.w, s[3][3]);
        }

        // ---- mask + scale + online softmax (row reductions across the 16 tx lanes)
        #pragma unroll
        for (int i = 0; i < 4; ++i) {
            int4 mm = *reinterpret_cast<const int4*>(
                mp + (size_t)(ty * 4 + i) * S + kbase + tx * 4);
            s[i][0] = mm.x ? s[i][0] * SCALE : NEGC;
            s[i][1] = mm.y ? s[i][1] * SCALE : NEGC;
            s[i][2] = mm.z ? s[i][2] * SCALE : NEGC;
            s[i][3] = mm.w ? s[i][3] * SCALE : NEGC;

            float mx = fmaxf(fmaxf(s[i][0], s[i][1]), fmaxf(s[i][2], s[i][3]));
            #pragma unroll
            for (int off = 8; off > 0; off >>= 1)
                mx = fmaxf(mx, __shfl_xor_sync(0xffffffffu, mx, off));

            const float mnew = fmaxf(m_i[i], mx);
            const float corr = __expf(m_i[i] - mnew);
            m_i[i] = mnew;

            float rs = 0.f;
            #pragma unroll
            for (int j = 0; j < 4; ++j) {
                s[i][j] = __expf(s[i][j] - mnew);
                rs += s[i][j];
            }
            #pragma unroll
            for (int off = 8; off > 0; off >>= 1)
                rs += __shfl_xor_sync(0xffffffffu, rs, off);

            l_i[i] = l_i[i] * corr + rs;
            #pragma unroll
            for (int j = 0; j < 4; ++j) acc[i][j] *= corr;
        }

        __syncthreads();   // done reading KPt as K-tile

        // ---- write P transposed into KPt: Pt[key][row]
        #pragma unroll
        for (int j = 0; j < 4; ++j)
            #pragma unroll
            for (int i = 0; i < 4; ++i)
                KPt[(tx * 4 + j) * PAD + ty * 4 + i] = s[i][j];
        __syncthreads();

        // ---- GEMM2: acc[i][j] += sum_k Pt[k][row] * Vs[k][dcol]
        #pragma unroll 8
        for (int kk = 0; kk < BN; ++kk) {
            float4 a  = *reinterpret_cast<const float4*>(KPt + kk * PAD + ty * 4);
            float4 bb = *reinterpret_cast<const float4*>(Vs  + kk * D   + tx * 4);
            acc[0][0] = fmaf(a.x, bb.x, acc[0][0]); acc[0][1] = fmaf(a.x, bb.y, acc[0][1]);
            acc[0][2] = fmaf(a.x, bb.z, acc[0][2]); acc[0][3] = fmaf(a.x, bb.w, acc[0][3]);
            acc[1][0] = fmaf(a.y, bb.x, acc[1][0]); acc[1][1] = fmaf(a.y, bb.y, acc[1][1]);
            acc[1][2] = fmaf(a.y, bb.z, acc[1][2]); acc[1][3] = fmaf(a.y, bb.w, acc[1][3]);
            acc[2][0] = fmaf(a.z, bb.x, acc[2][0]); acc[2][1] = fmaf(a.z, bb.y, acc[2][1]);
            acc[2][2] = fmaf(a.z, bb.z, acc[2][2]); acc[2][3] = fmaf(a.z, bb.w, acc[2][3]);
            acc[3][0] = fmaf(a.w, bb.x, acc[3][0]); acc[3][1] = fmaf(a.w, bb.y, acc[3][1]);
            acc[3][2] = fmaf(a.w, bb.z, acc[3][2]); acc[3][3] = fmaf(a.w, bb.w, acc[3][3]);
        }
        __syncthreads();   // before next tile overwrites KPt / Vs
    }

    // ---- epilogue: O = acc / l
    #pragma unroll
    for (int i = 0; i < 4; ++i) {
        const float inv = 1.0f / l_i[i];
        float4 o = make_float4(acc[i][0] * inv, acc[i][1] * inv,
                               acc[i][2] * inv, acc[i][3] * inv);
        *reinterpret_cast<float4*>(
            Out + ((size_t)bh * S + qbase + ty * 4 + i) * D + tx * 4) = o;
    }
}

extern "C" void kernel_launch(void* const* d_in, const int* in_sizes, int n_in,
                              void* d_out, int out_size)
{
    const float* q    = (const float*)d_in[0];
    const float* k    = (const float*)d_in[1];
    const float* v    = (const float*)d_in[2];
    const int*   mask = (const int*)d_in[3];
    float* out = (float*)d_out;

    constexpr int SMEM_BYTES = SMEM_FLOATS * (int)sizeof(float);  // 51200 > 48K default
    cudaFuncSetAttribute(attn_fwd, cudaFuncAttributeMaxDynamicSharedMemorySize, SMEM_BYTES);

    dim3 grid(S / BM, B * H);   // 32 x 64 = 2048 CTAs
    attn_fwd<<<grid, 256, SMEM_BYTES>>>(q, k, v, mask, out);
}

// round 4
// speedup vs baseline: 4.3541x; 4.3541x over previous
#include <cuda_runtime.h>
#include <cuda_fp16.h>
#include <cstdint>
#include <math.h>

// ---------------------------------------------------------------- problem
namespace {
constexpr int B = 4, H = 16, S = 2048, Dh = 64;
constexpr int BM = 128;          // query rows per CTA (8 warps x 16 rows)
constexpr int BN = 64;           // keys per tile
constexpr int TILES = S / BN;    // 32
constexpr float SCALE = 0.125f;  // 1/sqrt(64), folded into Q

// smem (floats): K double-buffered stride 72, V stride 68
constexpr int SK = 72, SV = 68;
constexpr int KOFF0 = 0, KOFF1 = 64 * SK;                 // 0, 4608
constexpr int VOFF0 = 2 * 64 * SK;                        // 9216
constexpr int VOFF1 = VOFF0 + 64 * SV;                    // 13568
constexpr int SMEM_FLOATS = VOFF1 + 64 * SV;              // 17920 -> 71680 B
}

// bit-packed mask: word index = (b*S + qrow)*64 + key/32
__device__ unsigned g_mbits[(size_t)B * S * (S / 32)];

// ---------------------------------------------------------------- helpers
__device__ __forceinline__ uint32_t smem_u32(const void* p) {
    uint32_t a;
    asm("{ .reg .u64 t; cvta.to.shared.u64 t, %1; cvt.u32.u64 %0, t; }" : "=r"(a) : "l"(p));
    return a;
}
// pack two f32 -> f16x2, lo = first arg (cvt.f16x2 puts operand A in the HIGH half)
__device__ __forceinline__ uint32_t packf16(float lo, float hi) {
    uint32_t d;
    asm("cvt.rn.f16x2.f32 %0, %1, %2;" : "=r"(d) : "f"(hi), "f"(lo));
    return d;
}
__device__ __forceinline__ void mma_f16(float* c, const uint32_t* a, const uint32_t* b) {
    asm volatile(
        "mma.sync.aligned.m16n8k16.row.col.f32.f16.f16.f32 "
        "{%0,%1,%2,%3}, {%4,%5,%6,%7}, {%8,%9}, {%0,%1,%2,%3};"
        : "+f"(c[0]), "+f"(c[1]), "+f"(c[2]), "+f"(c[3])
        : "r"(a[0]), "r"(a[1]), "r"(a[2]), "r"(a[3]), "r"(b[0]), "r"(b[1]));
}
#define CP16(dst, src) \
    asm volatile("cp.async.cg.shared.global [%0], [%1], 16;" :: "r"(dst), "l"(src) : "memory")
#define CP_COMMIT() asm volatile("cp.async.commit_group;" ::: "memory")
#define CP_WAIT(n)  asm volatile("cp.async.wait_group %0;" :: "n"(n) : "memory")

// ---------------------------------------------------------------- mask bit-pack
__global__ void pack_mask(const int* __restrict__ m) {
    unsigned gid = blockIdx.x * blockDim.x + threadIdx.x;
    unsigned bit = (m[gid] != 0) ? 1u : 0u;
    unsigned w = __ballot_sync(0xffffffffu, bit);
    if ((gid & 31u) == 0u) g_mbits[gid >> 5] = w;
}

// ---------------------------------------------------------------- attention
__global__ __launch_bounds__(256, 1) void attn_mma(
    const float* __restrict__ Q, const float* __restrict__ K,
    const float* __restrict__ V, float* __restrict__ Out)
{
    extern __shared__ float sm[];
    const uint32_t smb = smem_u32(sm);

    const int tid  = threadIdx.x;
    const int lane = tid & 31;
    const int wid  = tid >> 5;
    const int gid  = lane >> 2;        // group id: row-within-8 / n / key
    const int twoq = (lane & 3) * 2;   // 2 * thread-in-group

    const int bh = blockIdx.y;
    const int b  = bh >> 4;            // H == 16
    const int qbase = blockIdx.x * BM;
    const int qrow  = qbase + wid * 16 + gid;   // row0; row1 = qrow + 8

    const float* qp = Q + (size_t)bh * S * Dh;
    const float* kp = K + (size_t)bh * S * Dh;
    const float* vp = V + (size_t)bh * S * Dh;

    // cp.async staging: per buffer, 1024 16B-chunks for K and V each; 4 per thread
    const int st_row = tid >> 4;            // 0..15, +16 each j
    const int st_off = (tid & 15) * 4;      // float offset within row

    // ---- stage tile 0
    {
        #pragma unroll
        for (int j = 0; j < 4; ++j) {
            const int row = st_row + j * 16;
            CP16(smb + (uint32_t)(KOFF0 + row * SK + st_off) * 4, kp + row * Dh + st_off);
            CP16(smb + (uint32_t)(VOFF0 + row * SV + st_off) * 4, vp + row * Dh + st_off);
        }
        CP_COMMIT();
    }

    // ---- Q fragments (pre-scaled), reused for all tiles
    uint32_t qa[4][4];
    {
        const float* q0 = qp + (size_t)qrow * Dh;
        const float* q8 = q0 + 8 * Dh;
        #pragma unroll
        for (int kt = 0; kt < 4; ++kt) {
            const int d0 = kt * 16 + twoq;
            float2 x0 = *(const float2*)(q0 + d0);
            float2 x8 = *(const float2*)(q8 + d0);
            float2 y0 = *(const float2*)(q0 + d0 + 8);
            float2 y8 = *(const float2*)(q8 + d0 + 8);
            qa[kt][0] = packf16(x0.x * SCALE, x0.y * SCALE);
            qa[kt][1] = packf16(x8.x * SCALE, x8.y * SCALE);
            qa[kt][2] = packf16(y0.x * SCALE, y0.y * SCALE);
            qa[kt][3] = packf16(y8.x * SCALE, y8.y * SCALE);
        }
    }

    float of[8][4];
    #pragma unroll
    for (int nt = 0; nt < 8; ++nt)
        #pragma unroll
        for (int j = 0; j < 4; ++j) of[nt][j] = 0.f;
    float l0 = 0.f, l1 = 0.f;

    const unsigned* mrow = g_mbits + ((size_t)(b * S) + qrow) * (S / 32);

    for (int t = 0; t < TILES; ++t) {
        // ---- prefetch tile t+1 into the other buffer
        if (t + 1 < TILES) {
            const int koff = ((t + 1) & 1) ? KOFF1 : KOFF0;
            const int voff = ((t + 1) & 1) ? VOFF1 : VOFF0;
            const float* ks = kp + (size_t)(t + 1) * BN * Dh;
            const float* vs = vp + (size_t)(t + 1) * BN * Dh;
            #pragma unroll
            for (int j = 0; j < 4; ++j) {
                const int row = st_row + j * 16;
                CP16(smb + (uint32_t)(koff + row * SK + st_off) * 4, ks + row * Dh + st_off);
                CP16(smb + (uint32_t)(voff + row * SV + st_off) * 4, vs + row * Dh + st_off);
            }
            CP_COMMIT();
            CP_WAIT(1);
        } else {
            CP_WAIT(0);
        }

        // ---- mask words for this tile (issue early)
        uint2 mwa = *(const uint2*)(mrow + t * 2);
        uint2 mwb = *(const uint2*)(mrow + 8 * (S / 32) + t * 2);

        __syncthreads();
        const float* Kb = sm + ((t & 1) ? KOFF1 : KOFF0);
        const float* Vb = sm + ((t & 1) ? VOFF1 : VOFF0);

        // ---- MMA1: S = (Q*scale) K^T
        float sf[8][4];
        #pragma unroll
        for (int nt = 0; nt < 8; ++nt)
            #pragma unroll
            for (int j = 0; j < 4; ++j) sf[nt][j] = 0.f;

        #pragma unroll
        for (int kt = 0; kt < 4; ++kt) {
            #pragma unroll
            for (int nt = 0; nt < 8; ++nt) {
                const int key = nt * 8 + gid;
                const float* kr = Kb + key * SK + kt * 16 + twoq;
                float2 b0f = *(const float2*)kr;
                float2 b1f = *(const float2*)(kr + 8);
                uint32_t bb[2] = { packf16(b0f.x, b0f.y), packf16(b1f.x, b1f.y) };
                mma_f16(sf[nt], qa[kt], bb);
            }
        }

        // ---- mask + exp (unnormalized)
        #pragma unroll
        for (int nt = 0; nt < 8; ++nt) {
            const int sh = (nt & 3) * 8 + twoq;
            const unsigned wa = ((nt < 4) ? mwa.x : mwa.y) >> sh;
            const unsigned wb = ((nt < 4) ? mwb.x : mwb.y) >> sh;
            float e0 = (wa & 1u) ? __expf(sf[nt][0]) : 0.f;
            float e1 = (wa & 2u) ? __expf(sf[nt][1]) : 0.f;
            float e2 = (wb & 1u) ? __expf(sf[nt][2]) : 0.f;
            float e3 = (wb & 2u) ? __expf(sf[nt][3]) : 0.f;
            l0 += e0 + e1; l1 += e2 + e3;
            sf[nt][0] = e0; sf[nt][1] = e1; sf[nt][2] = e2; sf[nt][3] = e3;
        }

        // ---- P fragments: C layout maps directly onto A layout (pure cvt)
        uint32_t pa[4][4];
        #pragma unroll
        for (int kt = 0; kt < 4; ++kt) {
            pa[kt][0] = packf16(sf[2 * kt][0],     sf[2 * kt][1]);
            pa[kt][1] = packf16(sf[2 * kt][2],     sf[2 * kt][3]);
            pa[kt][2] = packf16(sf[2 * kt + 1][0], sf[2 * kt + 1][1]);
            pa[kt][3] = packf16(sf[2 * kt + 1][2], sf[2 * kt + 1][3]);
        }

        // ---- MMA2: O += P V
        #pragma unroll
        for (int kt = 0; kt < 4; ++kt) {
            #pragma unroll
            for (int nt = 0; nt < 8; ++nt) {
                const int krow = kt * 16 + twoq;
                const int dcol = nt * 8 + gid;
                uint32_t bb[2] = {
                    packf16(Vb[krow * SV + dcol],       Vb[(krow + 1) * SV + dcol]),
                    packf16(Vb[(krow + 8) * SV + dcol], Vb[(krow + 9) * SV + dcol])
                };
                mma_f16(of[nt], pa[kt], bb);
            }
        }
        __syncthreads();   // all reads of this buffer done before it is re-staged
    }

    // ---- epilogue: normalize and store
    l0 += __shfl_xor_sync(0xffffffffu, l0, 1);
    l0 += __shfl_xor_sync(0xffffffffu, l0, 2);
    l1 += __shfl_xor_sync(0xffffffffu, l1, 1);
    l1 += __shfl_xor_sync(0xffffffffu, l1, 2);
    const float inv0 = 1.0f / l0, inv1 = 1.0f / l1;

    float* o0 = Out + ((size_t)bh * S + qrow) * Dh;
    float* o8 = o0 + 8 * Dh;
    #pragma unroll
    for (int nt = 0; nt < 8; ++nt) {
        const int d = nt * 8 + twoq;
        *(float2*)(o0 + d) = make_float2(of[nt][0] * inv0, of[nt][1] * inv0);
        *(float2*)(o8 + d) = make_float2(of[nt][2] * inv1, of[nt][3] * inv1);
    }
}

// ---------------------------------------------------------------- launch
extern "C" void kernel_launch(void* const* d_in, const int* in_sizes, int n_in,
                              void* d_out, int out_size)
{
    const float* q    = (const float*)d_in[0];
    const float* k    = (const float*)d_in[1];
    const float* v    = (const float*)d_in[2];
    const int*   mask = (const int*)d_in[3];
    float* out = (float*)d_out;

    pack_mask<<<(B * S * S) / 256, 256>>>(mask);

    constexpr int SMEM_BYTES = SMEM_FLOATS * (int)sizeof(float);  // 71680
    cudaFuncSetAttribute(attn_mma, cudaFuncAttributeMaxDynamicSharedMemorySize, SMEM_BYTES);

    dim3 grid(S / BM, B * H);   // 16 x 64 = 1024 CTAs
    attn_mma<<<grid, 256, SMEM_BYTES>>>(q, k, v, out);
}

// round 5
// speedup vs baseline: 6.9140x; 1.5879x over previous
#include <cuda_runtime.h>
#include <cuda_fp16.h>
#include <cstdint>
#include <math.h>

// ---------------------------------------------------------------- problem
namespace {
constexpr int B = 4, H = 16, S = 2048, Dh = 64;
constexpr int BM = 128;          // query rows per CTA (8 warps x 16 rows)
constexpr int BN = 64;           // keys per tile
constexpr int TILES = S / BN;    // 32
constexpr float SCALE = 0.125f;  // 1/sqrt(64), folded into Q
constexpr size_t NELEM = (size_t)B * H * S * Dh;   // 8.39M

// smem layout (bytes): half tiles, 64 rows x 128B (64 halves), XOR-swizzled
constexpr int KOFF0 = 0;
constexpr int KOFF1 = 8192;
constexpr int VOFF0 = 16384;
constexpr int VOFF1 = 24576;
constexpr int SMEM_BYTES = 32768;
}

// scratch: bit-packed mask + fp16 K/V
__device__ unsigned g_mbits[(size_t)B * S * (S / 32)];
__device__ __half g_kh[NELEM];
__device__ __half g_vh[NELEM];

// ---------------------------------------------------------------- helpers
__device__ __forceinline__ uint32_t smem_u32(const void* p) {
    uint32_t a;
    asm("{ .reg .u64 t; cvta.to.shared.u64 t, %1; cvt.u32.u64 %0, t; }" : "=r"(a) : "l"(p));
    return a;
}
__device__ __forceinline__ uint32_t packf16(float lo, float hi) {
    uint32_t d;
    asm("cvt.rn.f16x2.f32 %0, %1, %2;" : "=r"(d) : "f"(hi), "f"(lo));
    return d;
}
__device__ __forceinline__ void mma_f16(float* c, const uint32_t* a, const uint32_t* b) {
    asm volatile(
        "mma.sync.aligned.m16n8k16.row.col.f32.f16.f16.f32 "
        "{%0,%1,%2,%3}, {%4,%5,%6,%7}, {%8,%9}, {%0,%1,%2,%3};"
        : "+f"(c[0]), "+f"(c[1]), "+f"(c[2]), "+f"(c[3])
        : "r"(a[0]), "r"(a[1]), "r"(a[2]), "r"(a[3]), "r"(b[0]), "r"(b[1]));
}
#define LDSM_X4(r0, r1, r2, r3, a)                                               \
    asm volatile("ldmatrix.sync.aligned.m8n8.x4.shared.b16 {%0,%1,%2,%3}, [%4];" \
                 : "=r"(r0), "=r"(r1), "=r"(r2), "=r"(r3) : "r"(a))
#define LDSM_X4_T(r0, r1, r2, r3, a)                                                   \
    asm volatile("ldmatrix.sync.aligned.m8n8.x4.trans.shared.b16 {%0,%1,%2,%3}, [%4];" \
                 : "=r"(r0), "=r"(r1), "=r"(r2), "=r"(r3) : "r"(a))
#define CP16(dst, src) \
    asm volatile("cp.async.cg.shared.global [%0], [%1], 16;" :: "r"(dst), "l"(src) : "memory")
#define CP_COMMIT() asm volatile("cp.async.commit_group;" ::: "memory")
#define CP_WAIT(n)  asm volatile("cp.async.wait_group %0;" :: "n"(n) : "memory")

// swizzled byte offset within a tile: row (key) 0..63, chunk (16B) 0..7
__device__ __forceinline__ uint32_t sw_off(int row, int chunk) {
    return (uint32_t)(row * 128 + ((chunk ^ (row & 7)) << 4));
}

// ---------------------------------------------------------------- pre-pass
__global__ void pack_mask(const int* __restrict__ m) {
    unsigned gid = blockIdx.x * blockDim.x + threadIdx.x;
    unsigned bit = (m[gid] != 0) ? 1u : 0u;
    unsigned w = __ballot_sync(0xffffffffu, bit);
    if ((gid & 31u) == 0u) g_mbits[gid >> 5] = w;
}
__global__ void cvt_half(const float* __restrict__ k, const float* __restrict__ v) {
    size_t i = ((size_t)blockIdx.x * blockDim.x + threadIdx.x) * 4;
    float4 tk = *reinterpret_cast<const float4*>(k + i);
    float4 tv = *reinterpret_cast<const float4*>(v + i);
    uint2 uk = make_uint2(packf16(tk.x, tk.y), packf16(tk.z, tk.w));
    uint2 uv = make_uint2(packf16(tv.x, tv.y), packf16(tv.z, tv.w));
    *reinterpret_cast<uint2*>(g_kh + i) = uk;
    *reinterpret_cast<uint2*>(g_vh + i) = uv;
}

// ---------------------------------------------------------------- attention
__global__ __launch_bounds__(256, 2) void attn_mma(
    const float* __restrict__ Q, float* __restrict__ Out)
{
    extern __shared__ char smc[];
    const uint32_t smb = smem_u32(smc);

    const int tid  = threadIdx.x;
    const int lane = tid & 31;
    const int wid  = tid >> 5;
    const int gid  = lane >> 2;        // 0..7
    const int twoq = (lane & 3) * 2;   // 0,2,4,6

    const int bh = blockIdx.y;
    const int b  = bh >> 4;            // H == 16
    const int qbase = blockIdx.x * BM;
    const int qrow  = qbase + wid * 16 + gid;   // row0; row1 = qrow + 8

    const float*  qp = Q + (size_t)bh * S * Dh;
    const __half* kp = g_kh + (size_t)bh * S * Dh;
    const __half* vp = g_vh + (size_t)bh * S * Dh;

    // staging: 512 16B-chunks per tensor per tile; 2 per thread
    // thread -> chunks {tid, tid+256}; chunk c: row = c>>3, cc = c&7
    const int c0r = tid >> 3,        c0c = tid & 7;          // chunk tid
    const int c1r = (tid + 256) >> 3, c1c = tid & 7;         // chunk tid+256

    // ---- stage tile 0
    CP16(smb + KOFF0 + sw_off(c0r, c0c), kp + c0r * Dh + c0c * 8);
    CP16(smb + KOFF0 + sw_off(c1r, c1c), kp + c1r * Dh + c1c * 8);
    CP16(smb + VOFF0 + sw_off(c0r, c0c), vp + c0r * Dh + c0c * 8);
    CP16(smb + VOFF0 + sw_off(c1r, c1c), vp + c1r * Dh + c1c * 8);
    CP_COMMIT();

    // ---- Q fragments (pre-scaled fp16), reused for all tiles
    uint32_t qa[4][4];
    {
        const float* q0 = qp + (size_t)qrow * Dh;
        const float* q8 = q0 + 8 * Dh;
        #pragma unroll
        for (int kt = 0; kt < 4; ++kt) {
            const int d0 = kt * 16 + twoq;
            float2 x0 = *(const float2*)(q0 + d0);
            float2 x8 = *(const float2*)(q8 + d0);
            float2 y0 = *(const float2*)(q0 + d0 + 8);
            float2 y8 = *(const float2*)(q8 + d0 + 8);
            qa[kt][0] = packf16(x0.x * SCALE, x0.y * SCALE);
            qa[kt][1] = packf16(x8.x * SCALE, x8.y * SCALE);
            qa[kt][2] = packf16(y0.x * SCALE, y0.y * SCALE);
            qa[kt][3] = packf16(y8.x * SCALE, y8.y * SCALE);
        }
    }

    float of[8][4];
    #pragma unroll
    for (int nt = 0; nt < 8; ++nt)
        #pragma unroll
        for (int j = 0; j < 4; ++j) of[nt][j] = 0.f;
    float l0 = 0.f, l1 = 0.f;

    const unsigned* mrow = g_mbits + ((size_t)(b * S) + qrow) * (S / 32);

    for (int t = 0; t < TILES; ++t) {
        // ---- prefetch tile t+1
        if (t + 1 < TILES) {
            const uint32_t ko = smb + (((t + 1) & 1) ? KOFF1 : KOFF0);
            const uint32_t vo = smb + (((t + 1) & 1) ? VOFF1 : VOFF0);
            const __half* ks = kp + (size_t)(t + 1) * BN * Dh;
            const __half* vs = vp + (size_t)(t + 1) * BN * Dh;
            CP16(ko + sw_off(c0r, c0c), ks + c0r * Dh + c0c * 8);
            CP16(ko + sw_off(c1r, c1c), ks + c1r * Dh + c1c * 8);
            CP16(vo + sw_off(c0r, c0c), vs + c0r * Dh + c0c * 8);
            CP16(vo + sw_off(c1r, c1c), vs + c1r * Dh + c1c * 8);
            CP_COMMIT();
            CP_WAIT(1);
        } else {
            CP_WAIT(0);
        }

        uint2 mwa = *(const uint2*)(mrow + t * 2);
        uint2 mwb = *(const uint2*)(mrow + 8 * (S / 32) + t * 2);

        __syncthreads();
        const uint32_t Kb = smb + ((t & 1) ? KOFF1 : KOFF0);
        const uint32_t Vb = smb + ((t & 1) ? VOFF1 : VOFF0);

        // ---- MMA1: S = (Q*scale) K^T ; B frags via ldmatrix (non-trans)
        float sf[8][4];
        #pragma unroll
        for (int nt = 0; nt < 8; ++nt)
            #pragma unroll
            for (int j = 0; j < 4; ++j) sf[nt][j] = 0.f;

        const int mat = lane >> 3, mr = lane & 7;
        #pragma unroll
        for (int kt = 0; kt < 4; ++kt) {
            #pragma unroll
            for (int ntp = 0; ntp < 4; ++ntp) {
                // m0,m1: keys ntp*16+mr (chunks 2kt, 2kt+1); m2,m3: keys +8
                const int key   = ntp * 16 + ((mat & 2) << 2) + mr;
                const int chunk = 2 * kt + (mat & 1);
                uint32_t b0, b1, b2, b3;
                LDSM_X4(b0, b1, b2, b3, Kb + sw_off(key, chunk));
                uint32_t f0[2] = { b0, b1 }, f1[2] = { b2, b3 };
                mma_f16(sf[2 * ntp],     qa[kt], f0);
                mma_f16(sf[2 * ntp + 1], qa[kt], f1);
            }
        }

        // ---- mask + exp (unnormalized)
        #pragma unroll
        for (int nt = 0; nt < 8; ++nt) {
            const int sh = (nt & 3) * 8 + twoq;
            const unsigned wa = ((nt < 4) ? mwa.x : mwa.y) >> sh;
            const unsigned wb = ((nt < 4) ? mwb.x : mwb.y) >> sh;
            float e0 = (wa & 1u) ? __expf(sf[nt][0]) : 0.f;
            float e1 = (wa & 2u) ? __expf(sf[nt][1]) : 0.f;
            float e2 = (wb & 1u) ? __expf(sf[nt][2]) : 0.f;
            float e3 = (wb & 2u) ? __expf(sf[nt][3]) : 0.f;
            l0 += e0 + e1; l1 += e2 + e3;
            sf[nt][0] = e0; sf[nt][1] = e1; sf[nt][2] = e2; sf[nt][3] = e3;
        }

        // ---- P fragments: C layout maps onto A layout (pure cvt)
        uint32_t pa[4][4];
        #pragma unroll
        for (int kt = 0; kt < 4; ++kt) {
            pa[kt][0] = packf16(sf[2 * kt][0],     sf[2 * kt][1]);
            pa[kt][1] = packf16(sf[2 * kt][2],     sf[2 * kt][3]);
            pa[kt][2] = packf16(sf[2 * kt + 1][0], sf[2 * kt + 1][1]);
            pa[kt][3] = packf16(sf[2 * kt + 1][2], sf[2 * kt + 1][3]);
        }

        // ---- MMA2: O += P V ; B frags via ldmatrix.trans
        #pragma unroll
        for (int kt = 0; kt < 4; ++kt) {
            #pragma unroll
            for (int ntp = 0; ntp < 4; ++ntp) {
                // m0: (keys kt*16+mr,   chunk 2ntp)   m1: (keys kt*16+8+mr, 2ntp)
                // m2: (keys kt*16+mr,   chunk 2ntp+1) m3: (keys kt*16+8+mr, 2ntp+1)
                const int key   = kt * 16 + ((mat & 1) << 3) + mr;
                const int chunk = 2 * ntp + (mat >> 1);
                uint32_t b0, b1, b2, b3;
                LDSM_X4_T(b0, b1, b2, b3, Vb + sw_off(key, chunk));
                uint32_t f0[2] = { b0, b1 }, f1[2] = { b2, b3 };
                mma_f16(of[2 * ntp],     pa[kt], f0);
                mma_f16(of[2 * ntp + 1], pa[kt], f1);
            }
        }
        __syncthreads();   // buffer reads done before re-staging
    }

    // ---- epilogue: normalize and store
    l0 += __shfl_xor_sync(0xffffffffu, l0, 1);
    l0 += __shfl_xor_sync(0xffffffffu, l0, 2);
    l1 += __shfl_xor_sync(0xffffffffu, l1, 1);
    l1 += __shfl_xor_sync(0xffffffffu, l1, 2);
    const float inv0 = 1.0f / l0, inv1 = 1.0f / l1;

    float* o0 = Out + ((size_t)bh * S + qrow) * Dh;
    float* o8 = o0 + 8 * Dh;
    #pragma unroll
    for (int nt = 0; nt < 8; ++nt) {
        const int d = nt * 8 + twoq;
        *(float2*)(o0 + d) = make_float2(of[nt][0] * inv0, of[nt][1] * inv0);
        *(float2*)(o8 + d) = make_float2(of[nt][2] * inv1, of[nt][3] * inv1);
    }
}

// ---------------------------------------------------------------- launch
extern "C" void kernel_launch(void* const* d_in, const int* in_sizes, int n_in,
                              void* d_out, int out_size)
{
    const float* q    = (const float*)d_in[0];
    const float* k    = (const float*)d_in[1];
    const float* v    = (const float*)d_in[2];
    const int*   mask = (const int*)d_in[3];
    float* out = (float*)d_out;

    pack_mask<<<(B * S * S) / 256, 256>>>(mask);
    cvt_half<<<(int)(NELEM / 4 / 256), 256>>>(k, v);

    cudaFuncSetAttribute(attn_mma, cudaFuncAttributeMaxDynamicSharedMemorySize, SMEM_BYTES);
    dim3 grid(S / BM, B * H);   // 16 x 64 = 1024 CTAs
    attn_mma<<<grid, 256, SMEM_BYTES>>>(q, out);
}